// round 16
// baseline (speedup 1.0000x reference)
#include <cuda_runtime.h>
#include <cuda_bf16.h>
#include <cstdint>

// ---------------- problem dims ----------------
#define B_ 4096
#define I_ 512
#define H_ 1024
#define G4 4096
#define KG 1536   // gates GEMM K (512 + 1024)
#define KC 1024   // cst GEMM K

// ---------------- scratch ----------------
__device__ float g_cst[(size_t)B_ * H_];
__device__ float g_bias[G4];                      // interleaved bias
__device__ __nv_bfloat16 gA_hi[(size_t)B_ * KG];
__device__ __nv_bfloat16 gA_lo[(size_t)B_ * KG];
__device__ __nv_bfloat16 gW_hi[(size_t)G4 * KG]; // interleaved rows n' = 4h+g
__device__ __nv_bfloat16 gW_lo[(size_t)G4 * KG];
__device__ __nv_bfloat16 gCx_hi[(size_t)B_ * KC];
__device__ __nv_bfloat16 gCx_lo[(size_t)B_ * KC];
__device__ __nv_bfloat16 gWd_hi[(size_t)H_ * KC];
__device__ __nv_bfloat16 gWd_lo[(size_t)H_ * KC];
__device__ unsigned int g_tile_ctr;
__device__ unsigned int g_cst_flag[512];

// ---------------- low-level helpers ----------------
__device__ __forceinline__ uint32_t smem_u32(const void* p) {
    uint32_t a;
    asm("{ .reg .u64 t; cvta.to.shared.u64 t, %1; cvt.u32.u64 %0, t; }" : "=r"(a) : "l"(p));
    return a;
}
__device__ __forceinline__ void cp16(uint32_t dst, const void* src) {
    asm volatile("cp.async.cg.shared.global [%0], [%1], 16;" :: "r"(dst), "l"(src));
}
__device__ __forceinline__ void cp_arrive(uint32_t bar) {
    asm volatile("cp.async.mbarrier.arrive.noinc.shared.b64 [%0];" :: "r"(bar) : "memory");
}
__device__ __forceinline__ void bar_arrive(uint32_t bar) {
    asm volatile("mbarrier.arrive.shared.b64 _, [%0];" :: "r"(bar) : "memory");
}
#define MBARRIER_INIT(addr, cnt) \
    asm volatile("mbarrier.init.shared.b64 [%0], %1;" :: "r"(addr), "r"((uint32_t)(cnt)) : "memory")

#define MBARRIER_WAIT_PARITY(addr, par) do {                                        \
    uint32_t _m = (addr); uint32_t _p = (par); uint32_t _d;                         \
    asm volatile("{\n\t.reg .pred p;\n\t"                                           \
        "mbarrier.try_wait.parity.acquire.cta.shared::cta.b64 p, [%1], %2;\n\t"     \
        "selp.b32 %0, 1, 0, p;\n\t}"                                                \
        : "=r"(_d) : "r"(_m), "r"(_p) : "memory");                                  \
    if (!_d) {                                                                      \
        asm volatile("{\n\t.reg .pred P1;\n\t"                                      \
            "WL_%=:\n\t"                                                            \
            "mbarrier.try_wait.parity.acquire.cta.shared::cta.b64 P1, [%0], %1, 0x989680;\n\t" \
            "@P1 bra.uni WD_%=;\n\tbra.uni WL_%=;\n\tWD_%=:\n\t}"                   \
            :: "r"(_m), "r"(_p) : "memory");                                        \
    }                                                                               \
} while (0)

__device__ __forceinline__ void ldm_x4(uint32_t* r, uint32_t addr) {
    asm volatile("ldmatrix.sync.aligned.m8n8.x4.shared.b16 {%0,%1,%2,%3}, [%4];"
                 : "=r"(r[0]), "=r"(r[1]), "=r"(r[2]), "=r"(r[3]) : "r"(addr));
}
__device__ __forceinline__ void mma_bf16(float* c, const uint32_t* a, const uint32_t* b) {
    asm volatile(
        "mma.sync.aligned.m16n8k16.row.col.f32.bf16.bf16.f32 "
        "{%0,%1,%2,%3}, {%4,%5,%6,%7}, {%8,%9}, {%0,%1,%2,%3};"
        : "+f"(c[0]), "+f"(c[1]), "+f"(c[2]), "+f"(c[3])
        : "r"(a[0]), "r"(a[1]), "r"(a[2]), "r"(a[3]), "r"(b[0]), "r"(b[1]));
}
__device__ __forceinline__ float sigmoidf_(float x) { return 1.0f / (1.0f + expf(-x)); }

// ---------------- GEMM tiling ----------------
// CTA tile 128x128, BKE=32 (64B/row + 16B pad = 80B stride). 8 warps (256 thr),
// warp tile 32x64 (wm=(wid&3)*32, wn=(wid>>2)*64). 2-stage mbarrier pipeline.
// 80KB smem/CTA -> 2 CTAs/SM; 16-long HMMA runs per dependent LDSM batch.
#define BKE 32
#define ROWB 80
#define OFF_AH 0
#define OFF_AL 10240                 // 128*80
#define OFF_BH 20480
#define OFF_BL 30720                 // + 128*80
#define STAGEB 40960
#define SMEM_DYN (2 * STAGEB)        // 81920

// One stage: A hi/lo 512 chunks16 each (2/thr), B hi/lo 512 each (2/thr) = 8 cp16/thr.
__device__ __forceinline__ void load_stage(
    uint32_t sb,
    const __nv_bfloat16* __restrict__ Ahi, const __nv_bfloat16* __restrict__ Alo,
    const __nv_bfloat16* __restrict__ Bhi, const __nv_bfloat16* __restrict__ Blo,
    int mBase, int nBase, int k0, int Ktot, int tid)
{
    #pragma unroll
    for (int i = 0; i < 2; ++i) {
        const int id  = tid + i * 256;      // 0..511
        const int row = id >> 2;            // 0..127
        const int c   = id & 3;
        const uint32_t doff = row * ROWB + c * 16;
        const size_t aoff = (size_t)(mBase + row) * Ktot + k0 + c * 8;
        const size_t boff = (size_t)(nBase + row) * Ktot + k0 + c * 8;
        cp16(sb + OFF_AH + doff, Ahi + aoff);
        cp16(sb + OFF_AL + doff, Alo + aoff);
        cp16(sb + OFF_BH + doff, Bhi + boff);
        cp16(sb + OFF_BL + doff, Blo + boff);
    }
}

// Consume one 32-K chunk from stage sb (warp tile 32x64). Arrives on `ebar`
// (one arrive, lane 0) right after the warp's LAST LDSM — the remaining MMAs
// read registers only, so the producer may overwrite the stage concurrently.
__device__ __forceinline__ void compute_chunk(
    uint32_t sb, uint32_t ebar,
    int aRow, int aCol, int bRow, int bCol, int lane, float acc[2][8][4])
{
    #pragma unroll
    for (int ks = 0; ks < 2; ++ks) {
        const int kb = ks * 32;
        uint32_t ah[2][4], al[2][4], b[4][4];
        // term 1: Ah * Bh
        #pragma unroll
        for (int mt = 0; mt < 2; ++mt)
            ldm_x4(ah[mt], sb + OFF_AH + (aRow + mt * 16) * ROWB + kb + aCol);
        #pragma unroll
        for (int nt = 0; nt < 4; ++nt)
            ldm_x4(b[nt], sb + OFF_BH + (bRow + nt * 16) * ROWB + kb + bCol);
        #pragma unroll
        for (int mt = 0; mt < 2; ++mt)
            #pragma unroll
            for (int nt = 0; nt < 8; ++nt)
                mma_bf16(acc[mt][nt], ah[mt], &b[nt >> 1][(nt & 1) * 2]);
        // term 2: Al * Bh (B regs still hold Bh)
        #pragma unroll
        for (int mt = 0; mt < 2; ++mt)
            ldm_x4(al[mt], sb + OFF_AL + (aRow + mt * 16) * ROWB + kb + aCol);
        #pragma unroll
        for (int mt = 0; mt < 2; ++mt)
            #pragma unroll
            for (int nt = 0; nt < 8; ++nt)
                mma_bf16(acc[mt][nt], al[mt], &b[nt >> 1][(nt & 1) * 2]);
        // term 3: Ah * Bl (reuse B regs)
        #pragma unroll
        for (int nt = 0; nt < 4; ++nt)
            ldm_x4(b[nt], sb + OFF_BL + (bRow + nt * 16) * ROWB + kb + bCol);
        if (ks == 1 && lane == 0) bar_arrive(ebar);   // last smem read done
        #pragma unroll
        for (int mt = 0; mt < 2; ++mt)
            #pragma unroll
            for (int nt = 0; nt < 8; ++nt)
                mma_bf16(acc[mt][nt], ah[mt], &b[nt >> 1][(nt & 1) * 2]);
    }
}

// 3-term bf16 mainloop over one 128x128 tile, 2-stage mbarrier pipeline.
// Caller must __syncthreads() before reusing stage smem after return.
__device__ __forceinline__ void run_mainloop(
    uint32_t smem_base, uint32_t mbar, int tid, int wid, int lane,
    const __nv_bfloat16* __restrict__ Ahi, const __nv_bfloat16* __restrict__ Alo,
    const __nv_bfloat16* __restrict__ Bhi, const __nv_bfloat16* __restrict__ Blo,
    int Ktot, int mBase, int nBase, float acc[2][8][4],
    int& pf0, int& pf1, int& pe0, int& pe1)
{
    const int wm = (wid & 3) * 32;
    const int wn = (wid >> 2) * 64;

    // prologue: chunks 0,1 -> stages 0,1 (caller's barrier guarantees stages free)
    load_stage(smem_base, Ahi, Alo, Bhi, Blo, mBase, nBase, 0, Ktot, tid);
    cp_arrive(mbar + 0);
    load_stage(smem_base + STAGEB, Ahi, Alo, Bhi, Blo, mBase, nBase, BKE, Ktot, tid);
    cp_arrive(mbar + 8);

    const int aRow = wm + (lane & 15);
    const int aCol = (lane & 16);
    const int bRow = wn + (lane & 7) + ((lane & 16) >> 1);
    const int bCol = (lane & 8) << 1;

    const int nch = Ktot / BKE;      // always even (32 or 48)
    for (int c = 0; c < nch; c += 2) {
        // ---- stage 0: chunk c ----
        MBARRIER_WAIT_PARITY(mbar + 0, pf0 & 1);
        pf0++;
        compute_chunk(smem_base, mbar + 16, aRow, aCol, bRow, bCol, lane, acc);
        if (c + 2 < nch) {
            MBARRIER_WAIT_PARITY(mbar + 16, pe0 & 1);
            pe0++;
            load_stage(smem_base, Ahi, Alo, Bhi, Blo, mBase, nBase,
                       (c + 2) * BKE, Ktot, tid);
            cp_arrive(mbar + 0);
        }
        // ---- stage 1: chunk c+1 ----
        MBARRIER_WAIT_PARITY(mbar + 8, pf1 & 1);
        pf1++;
        compute_chunk(smem_base + STAGEB, mbar + 24, aRow, aCol, bRow, bCol, lane, acc);
        if (c + 3 < nch) {
            MBARRIER_WAIT_PARITY(mbar + 24, pe1 & 1);
            pe1++;
            load_stage(smem_base + STAGEB, Ahi, Alo, Bhi, Blo, mBase, nBase,
                       (c + 3) * BKE, Ktot, tid);
            cp_arrive(mbar + 8);
        }
    }
    // one unconsumed empty flip per stage (last chunk on each stage)
    pe0++;
    pe1++;
}

// ---------------- persistent fused GEMM kernel ----------------
// Tiles 0..255: cst (128x128, grid 32 M x 8 N), sets done-flag.
// Tiles 256..1279: gates (128x128, 32 M x 32 N over n'=4h+g) + fused T-LSTM epilogue.
#define NT_CST 256u
#define NT_TOT 1280u

__global__ __launch_bounds__(256, 2) void fused_gemm_kernel(
    const float* __restrict__ tvec, const float* __restrict__ cx,
    const float* __restrict__ b_decomp, float* __restrict__ out)
{
    extern __shared__ char smem[];
    const uint32_t smem_base = smem_u32(smem);
    const int tid = threadIdx.x;
    const int wid = tid >> 5, lane = tid & 31;
    const int wm = (wid & 3) * 32;
    const int wn = (wid >> 2) * 64;
    const int rq = lane >> 2, cq = (lane & 3) * 2;
    __shared__ unsigned int s_tile;
    __shared__ __align__(8) uint64_t s_mbar[4];   // full0, full1, empty0, empty1
    const uint32_t mbar = smem_u32(&s_mbar[0]);

    if (tid < 2) MBARRIER_INIT(mbar + tid * 8, 256);       // full: all threads cp-arrive
    else if (tid < 4) MBARRIER_INIT(mbar + tid * 8, 8);    // empty: one arrive per warp
    __syncthreads();

    int pf0 = 0, pf1 = 0, pe0 = 0, pe1 = 0;

    for (;;) {
        __syncthreads();                       // smem quiesced from previous tile
        if (tid == 0) s_tile = atomicAdd(&g_tile_ctr, 1u);
        __syncthreads();
        const unsigned int t = s_tile;
        if (t >= NT_TOT) return;

        float acc[2][8][4];
        #pragma unroll
        for (int i = 0; i < 2; ++i)
            #pragma unroll
            for (int j = 0; j < 8; ++j)
                #pragma unroll
                for (int q = 0; q < 4; ++q) acc[i][j][q] = 0.0f;

        if (t < NT_CST) {
            // ---- cst tile: 32 x 8 grid of 128x128 ----
            const int mBase = (int)(t >> 3) * 128;
            const int nBase = (int)(t & 7) * 128;
            run_mainloop(smem_base, mbar, tid, wid, lane,
                         gCx_hi, gCx_lo, gWd_hi, gWd_lo, KC, mBase, nBase,
                         acc, pf0, pf1, pe0, pe1);
            #pragma unroll
            for (int mt = 0; mt < 2; ++mt) {
                const int row0 = mBase + wm + mt * 16 + rq;
                #pragma unroll
                for (int nt = 0; nt < 8; ++nt) {
                    const int col = nBase + wn + nt * 8 + cq;
                    const float b0 = b_decomp[col], b1 = b_decomp[col + 1];
                    float2 v0 = make_float2(tanhf(acc[mt][nt][0] + b0),
                                            tanhf(acc[mt][nt][1] + b1));
                    float2 v1 = make_float2(tanhf(acc[mt][nt][2] + b0),
                                            tanhf(acc[mt][nt][3] + b1));
                    *(float2*)&g_cst[(size_t)row0 * H_ + col]       = v0;
                    *(float2*)&g_cst[(size_t)(row0 + 8) * H_ + col] = v1;
                }
            }
            __threadfence();
            __syncthreads();
            if (tid == 0) atomicExch(&g_cst_flag[t], 1u);
        } else {
            // ---- gates tile: 32 M x 32 N; covers h in [bx*32, bx*32+32) ----
            const unsigned int g2 = t - NT_CST;
            const int bx = (int)(g2 & 31), by = (int)(g2 >> 5);
            const int mBase = by * 128, nBase = bx * 128;
            run_mainloop(smem_base, mbar, tid, wid, lane,
                         gA_hi, gA_lo, gW_hi, gW_lo, KG, mBase, nBase,
                         acc, pf0, pf1, pe0, pe1);
            // wait for the cst tile this epilogue reads (h block bx>>2)
            if (tid == 0) {
                const unsigned int f = (unsigned int)(by * 8 + (bx >> 2));
                while (atomicAdd(&g_cst_flag[f], 0u) == 0u) __nanosleep(64);
                __threadfence();
            }
            __syncthreads();   // all warps past mainloop -> stage smem reusable

            float* s_hy = (float*)smem;            // [128][33]
            float* s_cy = s_hy + 128 * 33;
            const bool even = !(lane & 1);
            #pragma unroll
            for (int mt = 0; mt < 2; ++mt) {
                #pragma unroll
                for (int nt = 0; nt < 8; ++nt) {
                    const int n0 = nBase + wn + nt * 8 + cq;
                    const float b0 = g_bias[n0], b1 = g_bias[n0 + 1];
                    const float c0 = acc[mt][nt][0] + b0, c1 = acc[mt][nt][1] + b1;
                    const float c2 = acc[mt][nt][2] + b0, c3 = acc[mt][nt][3] + b1;
                    const float x = __shfl_xor_sync(0xffffffffu, even ? c2 : c0, 1);
                    const float y = __shfl_xor_sync(0xffffffffu, even ? c3 : c1, 1);
                    float ig, fg, cg, og;
                    if (even) { ig = c0; fg = c1; cg = x;  og = y;  }
                    else      { ig = x;  fg = y;  cg = c2; og = c3; }
                    const int row_l = wm + mt * 16 + rq + (even ? 0 : 8);
                    const int h_loc = (wn + nt * 8 + (cq & 4)) >> 2;   // 0..31
                    const int row = mBase + row_l;
                    const int h = (nBase >> 2) + h_loc;

                    const float tb = tvec[row];
                    const float T = (tb != 0.0f) ? (1.0f / tb) : 0.0f;
                    const float cs = __ldcg(&g_cst[(size_t)row * H_ + h]);
                    const float cc = cx[(size_t)row * H_ + h];
                    const float cadj = cc - cs + T * cs;
                    const float cyv = sigmoidf_(fg) * cadj + sigmoidf_(ig) * tanhf(cg);
                    const float hyv = sigmoidf_(og) * tanhf(cyv);
                    s_hy[row_l * 33 + h_loc] = hyv;
                    s_cy[row_l * 33 + h_loc] = cyv;
                }
            }
            __syncthreads();
            #pragma unroll
            for (int i = 0; i < 16; ++i) {
                const int idx = tid + i * 256;      // 0..4095
                const int r = idx >> 5, hh = idx & 31;
                const size_t o = (size_t)(mBase + r) * H_ + (nBase >> 2) + hh;
                out[o] = s_hy[r * 33 + hh];
                out[(size_t)B_ * H_ + o] = s_cy[r * 33 + hh];
            }
        }
    }
}

// ---------------- single fused pack kernel ----------------
__device__ __forceinline__ void split_bf16(float v, __nv_bfloat16& h, __nv_bfloat16& l) {
    h = __float2bfloat16(v);
    l = __float2bfloat16(v - __bfloat162float(h));
}

__global__ __launch_bounds__(256) void pack_all_kernel(
    const float* __restrict__ input, const float* __restrict__ hx,
    const float* __restrict__ cx,
    const float* __restrict__ w_ih, const float* __restrict__ w_hh,
    const float* __restrict__ b_ih, const float* __restrict__ b_hh,
    const float* __restrict__ Wd)
{
    const int blk = blockIdx.x;
    const int tid = threadIdx.x;

    if (blk < 4096) {                       // pack A rows [input|hx]
        const int row = blk;
        #pragma unroll
        for (int i = 0; i < KG / 256; ++i) {
            const int k = tid + i * 256;
            const float v = (k < I_) ? input[(size_t)row * I_ + k]
                                     : hx[(size_t)row * H_ + (k - I_)];
            __nv_bfloat16 h, l; split_bf16(v, h, l);
            gA_hi[(size_t)row * KG + k] = h;
            gA_lo[(size_t)row * KG + k] = l;
        }
    } else if (blk < 8192) {                // pack W interleaved: n' = 4h+g
        const int np = blk - 4096;
        const int gg = np & 3, j = np >> 2;
        const int src = gg * H_ + j;
        #pragma unroll
        for (int i = 0; i < KG / 256; ++i) {
            const int k = tid + i * 256;
            const float v = (k < I_) ? w_ih[(size_t)src * I_ + k]
                                     : w_hh[(size_t)src * H_ + (k - I_)];
            __nv_bfloat16 h, l; split_bf16(v, h, l);
            gW_hi[(size_t)np * KG + k] = h;
            gW_lo[(size_t)np * KG + k] = l;
        }
    } else if (blk < 12288) {               // pack cx
        const int row = blk - 8192;
        #pragma unroll
        for (int i = 0; i < KC / 256; ++i) {
            const int k = tid + i * 256;
            const float v = cx[(size_t)row * KC + k];
            __nv_bfloat16 h, l; split_bf16(v, h, l);
            gCx_hi[(size_t)row * KC + k] = h;
            gCx_lo[(size_t)row * KC + k] = l;
        }
    } else if (blk < 13312) {               // Wd transpose + split
        __shared__ float tile[32][33];
        const int idx = blk - 12288;
        const int bx = (idx & 31) * 32, by = (idx >> 5) * 32;
        const int tx = tid & 31, ty = tid >> 5;    // 32 x 8
        #pragma unroll
        for (int i = 0; i < 32; i += 8)
            tile[ty + i][tx] = Wd[(size_t)(by + ty + i) * H_ + bx + tx];
        __syncthreads();
        #pragma unroll
        for (int i = 0; i < 32; i += 8) {
            const float v = tile[tx][ty + i];
            __nv_bfloat16 h, l; split_bf16(v, h, l);
            const size_t o = (size_t)(bx + ty + i) * KC + by + tx;
            gWd_hi[o] = h; gWd_lo[o] = l;
        }
    } else {                                // bias + reset
        #pragma unroll
        for (int i = 0; i < G4 / 256; ++i) {
            const int np = tid + i * 256;
            const int src = (np & 3) * H_ + (np >> 2);
            g_bias[np] = b_ih[src] + b_hh[src];
        }
        g_cst_flag[tid] = 0u;
        g_cst_flag[tid + 256] = 0u;
        if (tid == 0) g_tile_ctr = 0u;
    }
}

// ---------------- launch ----------------
extern "C" void kernel_launch(void* const* d_in, const int* in_sizes, int n_in,
                              void* d_out, int out_size) {
    const float* input     = (const float*)d_in[0];
    const float* t         = (const float*)d_in[1];
    const float* hx        = (const float*)d_in[2];
    const float* cx        = (const float*)d_in[3];
    const float* weight_ih = (const float*)d_in[4];
    const float* weight_hh = (const float*)d_in[5];
    const float* bias_ih   = (const float*)d_in[6];
    const float* bias_hh   = (const float*)d_in[7];
    const float* W_decomp  = (const float*)d_in[8];
    const float* b_decomp  = (const float*)d_in[9];
    float* out = (float*)d_out;

    cudaFuncSetAttribute(fused_gemm_kernel,
                         cudaFuncAttributeMaxDynamicSharedMemorySize, SMEM_DYN);

    pack_all_kernel<<<13313, 256>>>(input, hx, cx, weight_ih, weight_hh,
                                    bias_ih, bias_hh, W_decomp);

    fused_gemm_kernel<<<304, 256, SMEM_DYN>>>(t, cx, b_decomp, out);
}

// round 17
// speedup vs baseline: 1.0782x; 1.0782x over previous
#include <cuda_runtime.h>
#include <cuda_bf16.h>
#include <cstdint>

// ---------------- problem dims ----------------
#define B_ 4096
#define I_ 512
#define H_ 1024
#define G4 4096
#define KG 1536   // gates GEMM K (512 + 1024)
#define KC 1024   // cst GEMM K

// ---------------- scratch ----------------
__device__ float g_cst[(size_t)B_ * H_];
__device__ float g_bias[G4];                      // interleaved bias
__device__ __nv_bfloat16 gA_hi[(size_t)B_ * KG];
__device__ __nv_bfloat16 gA_lo[(size_t)B_ * KG];
__device__ __nv_bfloat16 gW_hi[(size_t)G4 * KG]; // interleaved rows n' = 4h+g
__device__ __nv_bfloat16 gW_lo[(size_t)G4 * KG];
__device__ __nv_bfloat16 gCx_hi[(size_t)B_ * KC];
__device__ __nv_bfloat16 gCx_lo[(size_t)B_ * KC];
__device__ __nv_bfloat16 gWd_hi[(size_t)H_ * KC];
__device__ __nv_bfloat16 gWd_lo[(size_t)H_ * KC];
__device__ unsigned int g_tile_ctr;
__device__ unsigned int g_cst_flag[512];

// ---------------- low-level helpers ----------------
__device__ __forceinline__ uint32_t smem_u32(const void* p) {
    uint32_t a;
    asm("{ .reg .u64 t; cvta.to.shared.u64 t, %1; cvt.u32.u64 %0, t; }" : "=r"(a) : "l"(p));
    return a;
}
__device__ __forceinline__ void cp16(uint32_t dst, const void* src) {
    asm volatile("cp.async.cg.shared.global [%0], [%1], 16;" :: "r"(dst), "l"(src));
}
__device__ __forceinline__ void cp_arrive(uint32_t bar) {
    asm volatile("cp.async.mbarrier.arrive.noinc.shared.b64 [%0];" :: "r"(bar) : "memory");
}
__device__ __forceinline__ void bar_arrive(uint32_t bar) {
    asm volatile("mbarrier.arrive.shared.b64 _, [%0];" :: "r"(bar) : "memory");
}
#define MBARRIER_INIT(addr, cnt) \
    asm volatile("mbarrier.init.shared.b64 [%0], %1;" :: "r"(addr), "r"((uint32_t)(cnt)) : "memory")

#define MBARRIER_WAIT_PARITY(addr, par) do {                                        \
    uint32_t _m = (addr); uint32_t _p = (par); uint32_t _d;                         \
    asm volatile("{\n\t.reg .pred p;\n\t"                                           \
        "mbarrier.try_wait.parity.acquire.cta.shared::cta.b64 p, [%1], %2;\n\t"     \
        "selp.b32 %0, 1, 0, p;\n\t}"                                                \
        : "=r"(_d) : "r"(_m), "r"(_p) : "memory");                                  \
    if (!_d) {                                                                      \
        asm volatile("{\n\t.reg .pred P1;\n\t"                                      \
            "WL_%=:\n\t"                                                            \
            "mbarrier.try_wait.parity.acquire.cta.shared::cta.b64 P1, [%0], %1, 0x989680;\n\t" \
            "@P1 bra.uni WD_%=;\n\tbra.uni WL_%=;\n\tWD_%=:\n\t}"                   \
            :: "r"(_m), "r"(_p) : "memory");                                        \
    }                                                                               \
} while (0)

__device__ __forceinline__ void ldm_x4(uint32_t* r, uint32_t addr) {
    asm volatile("ldmatrix.sync.aligned.m8n8.x4.shared.b16 {%0,%1,%2,%3}, [%4];"
                 : "=r"(r[0]), "=r"(r[1]), "=r"(r[2]), "=r"(r[3]) : "r"(addr));
}
__device__ __forceinline__ void mma_bf16(float* c, const uint32_t* a, const uint32_t* b) {
    asm volatile(
        "mma.sync.aligned.m16n8k16.row.col.f32.bf16.bf16.f32 "
        "{%0,%1,%2,%3}, {%4,%5,%6,%7}, {%8,%9}, {%0,%1,%2,%3};"
        : "+f"(c[0]), "+f"(c[1]), "+f"(c[2]), "+f"(c[3])
        : "r"(a[0]), "r"(a[1]), "r"(a[2]), "r"(a[3]), "r"(b[0]), "r"(b[1]));
}
__device__ __forceinline__ float sigmoidf_(float x) { return 1.0f / (1.0f + expf(-x)); }

// ---------------- GEMM tiling ----------------
// CTA tile 128x64, BKE=32 (rows packed at 64B with XOR swizzle — no pad).
// 8 warps (256 thr), warp tile 32x32. THREE-stage mbarrier pipeline.
// Stage = 24KB -> 3 stages = 72KB -> 3 CTAs/SM (24 warps).
// Swizzle: 16B chunk c of row r lives at c ^ ((r>>1)&3); conflict-free for
// ldmatrix (8 rows/phase hit 8 distinct 16B bank groups: parity picks the 64B
// half, (r>>1)&3 rotates within it) and for cp.async writes.
#define BKE 32
#define OFF_AH 0
#define OFF_AL 8192                  // 128*64
#define OFF_BH 16384
#define OFF_BL 20480                 // + 64*64
#define STAGEB 24576
#define NSTG 3
#define SMEM_DYN (NSTG * STAGEB)     // 73728

__device__ __forceinline__ uint32_t swz(uint32_t off) {
    return off ^ (((off >> 7) & 3u) << 4);
}

// One stage: A hi/lo 512 chunks16 each (2/thr), B hi/lo 256 each (1/thr) = 6 cp16/thr.
__device__ __forceinline__ void load_stage(
    uint32_t sb,
    const __nv_bfloat16* __restrict__ Ahi, const __nv_bfloat16* __restrict__ Alo,
    const __nv_bfloat16* __restrict__ Bhi, const __nv_bfloat16* __restrict__ Blo,
    int mBase, int nBase, int k0, int Ktot, int tid)
{
    #pragma unroll
    for (int i = 0; i < 2; ++i) {
        const int id  = tid + i * 256;      // 0..511
        const int row = id >> 2;            // 0..127
        const int c   = id & 3;
        const uint32_t doff = swz(row * 64 + c * 16);
        const size_t aoff = (size_t)(mBase + row) * Ktot + k0 + c * 8;
        cp16(sb + OFF_AH + doff, Ahi + aoff);
        cp16(sb + OFF_AL + doff, Alo + aoff);
    }
    {
        const int row = tid >> 2;           // 0..63
        const int c   = tid & 3;
        const uint32_t doff = swz(row * 64 + c * 16);
        const size_t boff = (size_t)(nBase + row) * Ktot + k0 + c * 8;
        cp16(sb + OFF_BH + doff, Bhi + boff);
        cp16(sb + OFF_BL + doff, Blo + boff);
    }
}

// Consume one 32-K chunk from stage sb. Arrives on `ebar` (one arrive, lane 0)
// right after the warp's LAST LDSM — remaining MMAs read registers only.
__device__ __forceinline__ void compute_chunk(
    uint32_t sb, uint32_t ebar,
    int aRow, int aCol, int bRow, int bCol, int lane, float acc[2][4][4])
{
    // per-row swizzle bases (row fixed per mt/nt; column XOR precomputed)
    uint32_t baseA[2], baseB[2];
    #pragma unroll
    for (int mt = 0; mt < 2; ++mt) {
        const int r = aRow + mt * 16;
        baseA[mt] = sb + r * 64 + ((((uint32_t)r >> 1) & 3u) << 4);  // XOR folded below
    }
    #pragma unroll
    for (int nt = 0; nt < 2; ++nt) {
        const int r = bRow + nt * 16;
        baseB[nt] = sb + r * 64 + ((((uint32_t)r >> 1) & 3u) << 4);
    }
    // NOTE: column = kc ^ xr where xr = ((r>>1)&3)<<4. Since base holds +xr and
    // kc^xr = kc + xr - 2*(kc&xr), we can't just add; compute addr explicitly.
    #pragma unroll
    for (int ks = 0; ks < 2; ++ks) {
        const int kb = ks * 32;
        const uint32_t kcA = (uint32_t)(kb + aCol);
        const uint32_t kcB = (uint32_t)(kb + bCol);
        uint32_t ah[2][4], al[2][4], b[2][4];
        // term 1: Ah * Bh
        #pragma unroll
        for (int mt = 0; mt < 2; ++mt) {
            const int r = aRow + mt * 16;
            const uint32_t xr = (((uint32_t)r >> 1) & 3u) << 4;
            ldm_x4(ah[mt], sb + OFF_AH + r * 64 + (kcA ^ xr));
        }
        #pragma unroll
        for (int nt = 0; nt < 2; ++nt) {
            const int r = bRow + nt * 16;
            const uint32_t xr = (((uint32_t)r >> 1) & 3u) << 4;
            ldm_x4(b[nt], sb + OFF_BH + r * 64 + (kcB ^ xr));
        }
        #pragma unroll
        for (int mt = 0; mt < 2; ++mt)
            #pragma unroll
            for (int nt = 0; nt < 4; ++nt)
                mma_bf16(acc[mt][nt], ah[mt], &b[nt >> 1][(nt & 1) * 2]);
        // term 2: Al * Bh
        #pragma unroll
        for (int mt = 0; mt < 2; ++mt) {
            const int r = aRow + mt * 16;
            const uint32_t xr = (((uint32_t)r >> 1) & 3u) << 4;
            ldm_x4(al[mt], sb + OFF_AL + r * 64 + (kcA ^ xr));
        }
        #pragma unroll
        for (int mt = 0; mt < 2; ++mt)
            #pragma unroll
            for (int nt = 0; nt < 4; ++nt)
                mma_bf16(acc[mt][nt], al[mt], &b[nt >> 1][(nt & 1) * 2]);
        // term 3: Ah * Bl (reuse B regs)
        #pragma unroll
        for (int nt = 0; nt < 2; ++nt) {
            const int r = bRow + nt * 16;
            const uint32_t xr = (((uint32_t)r >> 1) & 3u) << 4;
            ldm_x4(b[nt], sb + OFF_BL + r * 64 + (kcB ^ xr));
        }
        if (ks == 1 && lane == 0) bar_arrive(ebar);   // last smem read done
        #pragma unroll
        for (int mt = 0; mt < 2; ++mt)
            #pragma unroll
            for (int nt = 0; nt < 4; ++nt)
                mma_bf16(acc[mt][nt], ah[mt], &b[nt >> 1][(nt & 1) * 2]);
    }
    (void)baseA; (void)baseB;
}

// Process one chunk on a compile-time stage: wait full, compute, refill c+3.
#define PROC_STAGE(S, PF, PE)                                                     \
    do {                                                                          \
        MBARRIER_WAIT_PARITY(mbar + (S) * 8, (PF) & 1);                           \
        (PF)++;                                                                   \
        compute_chunk(smem_base + (S) * STAGEB, mbar + 24 + (S) * 8,              \
                      aRow, aCol, bRow, bCol, lane, acc);                         \
        if (c + NSTG < nch) {                                                     \
            MBARRIER_WAIT_PARITY(mbar + 24 + (S) * 8, (PE) & 1);                  \
            (PE)++;                                                               \
            load_stage(smem_base + (S) * STAGEB, Ahi, Alo, Bhi, Blo,              \
                       mBase, nBase, (c + NSTG) * BKE, Ktot, tid);                \
            cp_arrive(mbar + (S) * 8);                                            \
        }                                                                         \
    } while (0)

// 3-term bf16 mainloop, 3-stage mbarrier pipeline. Caller must __syncthreads()
// before reusing stage smem after return.
__device__ __forceinline__ void run_mainloop(
    uint32_t smem_base, uint32_t mbar, int tid, int wid, int lane,
    const __nv_bfloat16* __restrict__ Ahi, const __nv_bfloat16* __restrict__ Alo,
    const __nv_bfloat16* __restrict__ Bhi, const __nv_bfloat16* __restrict__ Blo,
    int Ktot, int mBase, int nBase, float acc[2][4][4],
    int& pf0, int& pf1, int& pf2, int& pe0, int& pe1, int& pe2)
{
    const int wm = (wid & 3) * 32;
    const int wn = (wid >> 2) * 32;

    // prologue: chunks 0,1,2 -> stages 0,1,2 (caller's barrier: stages free)
    load_stage(smem_base, Ahi, Alo, Bhi, Blo, mBase, nBase, 0, Ktot, tid);
    cp_arrive(mbar + 0);
    load_stage(smem_base + STAGEB, Ahi, Alo, Bhi, Blo, mBase, nBase, BKE, Ktot, tid);
    cp_arrive(mbar + 8);
    load_stage(smem_base + 2 * STAGEB, Ahi, Alo, Bhi, Blo, mBase, nBase, 2 * BKE, Ktot, tid);
    cp_arrive(mbar + 16);

    const int aRow = wm + (lane & 15);
    const int aCol = (lane & 16);
    const int bRow = wn + (lane & 7) + ((lane & 16) >> 1);
    const int bCol = (lane & 8) << 1;

    const int nch = Ktot / BKE;      // 32 or 48
    int c = 0;
    while (c < nch) {
        PROC_STAGE(0, pf0, pe0);
        ++c; if (c >= nch) break;
        PROC_STAGE(1, pf1, pe1);
        ++c; if (c >= nch) break;
        PROC_STAGE(2, pf2, pe2);
        ++c;
    }
    // one unconsumed empty flip per stage (last chunk on each stage)
    pe0++; pe1++; pe2++;
}

// ---------------- persistent fused GEMM kernel ----------------
// Tiles 0..511: cst (128x64, grid 32 M x 16 N), sets done-flag.
// Tiles 512..2559: gates (128x64, 32 M x 64 N over n'=4h+g) + fused T-LSTM epilogue.
#define NT_CST 512u
#define NT_TOT 2560u

__global__ __launch_bounds__(256, 3) void fused_gemm_kernel(
    const float* __restrict__ tvec, const float* __restrict__ cx,
    const float* __restrict__ b_decomp, float* __restrict__ out)
{
    extern __shared__ __align__(128) char smem[];
    const uint32_t smem_base = smem_u32(smem);
    const int tid = threadIdx.x;
    const int wid = tid >> 5, lane = tid & 31;
    const int wm = (wid & 3) * 32;
    const int wn = (wid >> 2) * 32;
    const int rq = lane >> 2, cq = (lane & 3) * 2;
    __shared__ unsigned int s_tile;
    __shared__ __align__(8) uint64_t s_mbar[6];   // full0..2, empty0..2
    const uint32_t mbar = smem_u32(&s_mbar[0]);

    if (tid < 3) MBARRIER_INIT(mbar + tid * 8, 256);            // full
    else if (tid < 6) MBARRIER_INIT(mbar + tid * 8, 8);         // empty (at +24)
    __syncthreads();

    int pf0 = 0, pf1 = 0, pf2 = 0, pe0 = 0, pe1 = 0, pe2 = 0;

    for (;;) {
        __syncthreads();                       // smem quiesced from previous tile
        if (tid == 0) s_tile = atomicAdd(&g_tile_ctr, 1u);
        __syncthreads();
        const unsigned int t = s_tile;
        if (t >= NT_TOT) return;

        float acc[2][4][4];
        #pragma unroll
        for (int i = 0; i < 2; ++i)
            #pragma unroll
            for (int j = 0; j < 4; ++j)
                #pragma unroll
                for (int q = 0; q < 4; ++q) acc[i][j][q] = 0.0f;

        if (t < NT_CST) {
            // ---- cst tile: 32 x 16 grid of 128x64 ----
            const int mBase = (int)(t >> 4) * 128;
            const int nBase = (int)(t & 15) * 64;
            run_mainloop(smem_base, mbar, tid, wid, lane,
                         gCx_hi, gCx_lo, gWd_hi, gWd_lo, KC, mBase, nBase,
                         acc, pf0, pf1, pf2, pe0, pe1, pe2);
            #pragma unroll
            for (int mt = 0; mt < 2; ++mt) {
                const int row0 = mBase + wm + mt * 16 + rq;
                #pragma unroll
                for (int nt = 0; nt < 4; ++nt) {
                    const int col = nBase + wn + nt * 8 + cq;
                    const float b0 = b_decomp[col], b1 = b_decomp[col + 1];
                    float2 v0 = make_float2(tanhf(acc[mt][nt][0] + b0),
                                            tanhf(acc[mt][nt][1] + b1));
                    float2 v1 = make_float2(tanhf(acc[mt][nt][2] + b0),
                                            tanhf(acc[mt][nt][3] + b1));
                    *(float2*)&g_cst[(size_t)row0 * H_ + col]       = v0;
                    *(float2*)&g_cst[(size_t)(row0 + 8) * H_ + col] = v1;
                }
            }
            __threadfence();
            __syncthreads();
            if (tid == 0) atomicExch(&g_cst_flag[t], 1u);
        } else {
            // ---- gates tile: 32 M x 64 N; covers h in [bx*16, bx*16+16) ----
            const unsigned int g2 = t - NT_CST;
            const int bx = (int)(g2 & 63), by = (int)(g2 >> 6);
            const int mBase = by * 128, nBase = bx * 64;
            run_mainloop(smem_base, mbar, tid, wid, lane,
                         gA_hi, gA_lo, gW_hi, gW_lo, KG, mBase, nBase,
                         acc, pf0, pf1, pf2, pe0, pe1, pe2);
            // wait for the cst tile this epilogue reads
            if (tid == 0) {
                const unsigned int f = (unsigned int)(by * 16 + (bx >> 2));
                while (atomicAdd(&g_cst_flag[f], 0u) == 0u) __nanosleep(64);
                __threadfence();
            }
            __syncthreads();   // all warps past mainloop -> stage smem reusable

            float* s_hy = (float*)smem;            // [128][17]
            float* s_cy = s_hy + 128 * 17;
            const bool even = !(lane & 1);
            #pragma unroll
            for (int mt = 0; mt < 2; ++mt) {
                #pragma unroll
                for (int nt = 0; nt < 4; ++nt) {
                    const int n0 = nBase + wn + nt * 8 + cq;
                    const float b0 = g_bias[n0], b1 = g_bias[n0 + 1];
                    const float c0 = acc[mt][nt][0] + b0, c1 = acc[mt][nt][1] + b1;
                    const float c2 = acc[mt][nt][2] + b0, c3 = acc[mt][nt][3] + b1;
                    const float x = __shfl_xor_sync(0xffffffffu, even ? c2 : c0, 1);
                    const float y = __shfl_xor_sync(0xffffffffu, even ? c3 : c1, 1);
                    float ig, fg, cg, og;
                    if (even) { ig = c0; fg = c1; cg = x;  og = y;  }
                    else      { ig = x;  fg = y;  cg = c2; og = c3; }
                    const int row_l = wm + mt * 16 + rq + (even ? 0 : 8);
                    const int h_loc = (wn + nt * 8 + (cq & 4)) >> 2;   // 0..15
                    const int row = mBase + row_l;
                    const int h = (nBase >> 2) + h_loc;

                    const float tb = tvec[row];
                    const float T = (tb != 0.0f) ? (1.0f / tb) : 0.0f;
                    const float cs = __ldcg(&g_cst[(size_t)row * H_ + h]);
                    const float cc = cx[(size_t)row * H_ + h];
                    const float cadj = cc - cs + T * cs;
                    const float cyv = sigmoidf_(fg) * cadj + sigmoidf_(ig) * tanhf(cg);
                    const float hyv = sigmoidf_(og) * tanhf(cyv);
                    s_hy[row_l * 17 + h_loc] = hyv;
                    s_cy[row_l * 17 + h_loc] = cyv;
                }
            }
            __syncthreads();
            #pragma unroll
            for (int i = 0; i < 8; ++i) {
                const int idx = tid + i * 256;      // 0..2047
                const int r = idx >> 4, hh = idx & 15;
                const size_t o = (size_t)(mBase + r) * H_ + (nBase >> 2) + hh;
                out[o] = s_hy[r * 17 + hh];
                out[(size_t)B_ * H_ + o] = s_cy[r * 17 + hh];
            }
        }
    }
}

// ---------------- single fused pack kernel ----------------
__device__ __forceinline__ void split_bf16(float v, __nv_bfloat16& h, __nv_bfloat16& l) {
    h = __float2bfloat16(v);
    l = __float2bfloat16(v - __bfloat162float(h));
}

__global__ __launch_bounds__(256) void pack_all_kernel(
    const float* __restrict__ input, const float* __restrict__ hx,
    const float* __restrict__ cx,
    const float* __restrict__ w_ih, const float* __restrict__ w_hh,
    const float* __restrict__ b_ih, const float* __restrict__ b_hh,
    const float* __restrict__ Wd)
{
    const int blk = blockIdx.x;
    const int tid = threadIdx.x;

    if (blk < 4096) {                       // pack A rows [input|hx]
        const int row = blk;
        #pragma unroll
        for (int i = 0; i < KG / 256; ++i) {
            const int k = tid + i * 256;
            const float v = (k < I_) ? input[(size_t)row * I_ + k]
                                     : hx[(size_t)row * H_ + (k - I_)];
            __nv_bfloat16 h, l; split_bf16(v, h, l);
            gA_hi[(size_t)row * KG + k] = h;
            gA_lo[(size_t)row * KG + k] = l;
        }
    } else if (blk < 8192) {                // pack W interleaved: n' = 4h+g
        const int np = blk - 4096;
        const int gg = np & 3, j = np >> 2;
        const int src = gg * H_ + j;
        #pragma unroll
        for (int i = 0; i < KG / 256; ++i) {
            const int k = tid + i * 256;
            const float v = (k < I_) ? w_ih[(size_t)src * I_ + k]
                                     : w_hh[(size_t)src * H_ + (k - I_)];
            __nv_bfloat16 h, l; split_bf16(v, h, l);
            gW_hi[(size_t)np * KG + k] = h;
            gW_lo[(size_t)np * KG + k] = l;
        }
    } else if (blk < 12288) {               // pack cx
        const int row = blk - 8192;
        #pragma unroll
        for (int i = 0; i < KC / 256; ++i) {
            const int k = tid + i * 256;
            const float v = cx[(size_t)row * KC + k];
            __nv_bfloat16 h, l; split_bf16(v, h, l);
            gCx_hi[(size_t)row * KC + k] = h;
            gCx_lo[(size_t)row * KC + k] = l;
        }
    } else if (blk < 13312) {               // Wd transpose + split
        __shared__ float tile[32][33];
        const int idx = blk - 12288;
        const int bx = (idx & 31) * 32, by = (idx >> 5) * 32;
        const int tx = tid & 31, ty = tid >> 5;    // 32 x 8
        #pragma unroll
        for (int i = 0; i < 32; i += 8)
            tile[ty + i][tx] = Wd[(size_t)(by + ty + i) * H_ + bx + tx];
        __syncthreads();
        #pragma unroll
        for (int i = 0; i < 32; i += 8) {
            const float v = tile[tx][ty + i];
            __nv_bfloat16 h, l; split_bf16(v, h, l);
            const size_t o = (size_t)(bx + ty + i) * KC + by + tx;
            gWd_hi[o] = h; gWd_lo[o] = l;
        }
    } else {                                // bias + reset
        #pragma unroll
        for (int i = 0; i < G4 / 256; ++i) {
            const int np = tid + i * 256;
            const int src = (np & 3) * H_ + (np >> 2);
            g_bias[np] = b_ih[src] + b_hh[src];
        }
        g_cst_flag[tid] = 0u;
        g_cst_flag[tid + 256] = 0u;
        if (tid == 0) g_tile_ctr = 0u;
    }
}

// ---------------- launch ----------------
extern "C" void kernel_launch(void* const* d_in, const int* in_sizes, int n_in,
                              void* d_out, int out_size) {
    const float* input     = (const float*)d_in[0];
    const float* t         = (const float*)d_in[1];
    const float* hx        = (const float*)d_in[2];
    const float* cx        = (const float*)d_in[3];
    const float* weight_ih = (const float*)d_in[4];
    const float* weight_hh = (const float*)d_in[5];
    const float* bias_ih   = (const float*)d_in[6];
    const float* bias_hh   = (const float*)d_in[7];
    const float* W_decomp  = (const float*)d_in[8];
    const float* b_decomp  = (const float*)d_in[9];
    float* out = (float*)d_out;

    cudaFuncSetAttribute(fused_gemm_kernel,
                         cudaFuncAttributeMaxDynamicSharedMemorySize, SMEM_DYN);

    pack_all_kernel<<<13313, 256>>>(input, hx, cx, weight_ih, weight_hh,
                                    bias_ih, bias_hh, W_decomp);

    fused_gemm_kernel<<<456, 256, SMEM_DYN>>>(t, cx, b_decomp, out);
}